// round 9
// baseline (speedup 1.0000x reference)
#include <cuda_runtime.h>
#include <cuda_bf16.h>
#include <cstdint>
#include <math.h>

// Problem constants
#define BB 64
#define SS 512
#define II 512
#define HH 512
#define LL 2
#define MROWS (BB * LL)          // 128 recurrence rows
#define MX (BB * SS)             // 32768 rows of xa GEMM

// ---------------- scratch (static device memory; no allocs allowed) ----------
__device__ float g_xa[(size_t)MX * HH];        // 64 MB: xa = x @ W_ih^T + b_ih
// h slices: [buf][rb][gb][8 rows * 64 cols]  (256 KB, L2-resident)
__device__ float g_hsl[2][16][8][512];
// per-producer flags, monotonic step values within a launch (reset each launch)
__device__ unsigned g_flag[16][8];

// =============================================================================
// Kernel R: reset flags (runs first every launch; makes replays correct)
// =============================================================================
__global__ void reset_flags_kernel()
{
    if (threadIdx.x < 128)
        ((unsigned*)g_flag)[threadIdx.x] = 0u;
}

// =============================================================================
// Kernel A: xa[m][n] = sum_k x[m][k] * W_ih[n][k] + b_ih[n]
// 128x128 tile, BK=8, double buffered, 8x8 per thread, 256 threads.
// =============================================================================
__global__ void __launch_bounds__(256) gemm_xa_kernel(
    const float* __restrict__ A,      // [MX][II]
    const float* __restrict__ Bw,     // [HH][II]
    const float* __restrict__ bias)   // [HH]
{
    __shared__ float As[2][8][128];
    __shared__ float Bs[2][8][128];

    const int K = II;
    const int N = HH;
    const int m0 = blockIdx.y * 128;
    const int n0 = blockIdx.x * 128;
    const int tid = threadIdx.x;
    const int tx = tid & 15;
    const int ty = tid >> 4;
    const int lrow = tid >> 1;
    const int lkq  = (tid & 1) * 4;

    const float* Aptr = A + (size_t)(m0 + lrow) * K + lkq;
    const float* Bptr = Bw + (size_t)(n0 + lrow) * K + lkq;

    float acc[8][8];
#pragma unroll
    for (int i = 0; i < 8; i++)
#pragma unroll
        for (int j = 0; j < 8; j++) acc[i][j] = 0.f;

    {
        float4 av = *(const float4*)Aptr;
        float4 bv = *(const float4*)Bptr;
        As[0][lkq + 0][lrow] = av.x; As[0][lkq + 1][lrow] = av.y;
        As[0][lkq + 2][lrow] = av.z; As[0][lkq + 3][lrow] = av.w;
        Bs[0][lkq + 0][lrow] = bv.x; Bs[0][lkq + 1][lrow] = bv.y;
        Bs[0][lkq + 2][lrow] = bv.z; Bs[0][lkq + 3][lrow] = bv.w;
    }
    __syncthreads();

    for (int kb = 8; kb <= K; kb += 8) {
        const int buf = ((kb >> 3) & 1) ^ 1;
        float4 av2, bv2;
        const bool more = (kb < K);
        if (more) {
            av2 = *(const float4*)(Aptr + kb);
            bv2 = *(const float4*)(Bptr + kb);
        }
#pragma unroll
        for (int kk = 0; kk < 8; kk++) {
            float a[8], b[8];
            *(float4*)(a + 0) = *(const float4*)&As[buf][kk][ty * 8 + 0];
            *(float4*)(a + 4) = *(const float4*)&As[buf][kk][ty * 8 + 4];
            *(float4*)(b + 0) = *(const float4*)&Bs[buf][kk][tx * 8 + 0];
            *(float4*)(b + 4) = *(const float4*)&Bs[buf][kk][tx * 8 + 4];
#pragma unroll
            for (int i = 0; i < 8; i++)
#pragma unroll
                for (int j = 0; j < 8; j++)
                    acc[i][j] += a[i] * b[j];
        }
        if (more) {
            const int nb = buf ^ 1;
            As[nb][lkq + 0][lrow] = av2.x; As[nb][lkq + 1][lrow] = av2.y;
            As[nb][lkq + 2][lrow] = av2.z; As[nb][lkq + 3][lrow] = av2.w;
            Bs[nb][lkq + 0][lrow] = bv2.x; Bs[nb][lkq + 1][lrow] = bv2.y;
            Bs[nb][lkq + 2][lrow] = bv2.z; Bs[nb][lkq + 3][lrow] = bv2.w;
            __syncthreads();
        }
    }

    float4 bv0 = *(const float4*)&bias[n0 + tx * 8 + 0];
    float4 bv1 = *(const float4*)&bias[n0 + tx * 8 + 4];
#pragma unroll
    for (int i = 0; i < 8; i++) {
        float* Crow = g_xa + (size_t)(m0 + ty * 8 + i) * N + n0 + tx * 8;
        float4 c0, c1;
        c0.x = acc[i][0] + bv0.x; c0.y = acc[i][1] + bv0.y;
        c0.z = acc[i][2] + bv0.z; c0.w = acc[i][3] + bv0.w;
        c1.x = acc[i][4] + bv1.x; c1.y = acc[i][5] + bv1.y;
        c1.z = acc[i][6] + bv1.z; c1.w = acc[i][7] + bv1.w;
        *(float4*)(Crow + 0) = c0;
        *(float4*)(Crow + 4) = c1;
    }
}

// =============================================================================
// Kernel B: persistent recurrence, v6 (per-producer flags, warp pipeline).
// 128 CTAs = 16 row-groups (rb) x 8 col-blocks (gb).
// CTA (rb,gb): rows rb*8..+7, cols gb*64..+63, K=512.
// Consumer warp kq only needs the 2 KB slice from producer CTA (rb,kq):
// it spins on that producer's flag (monotonic step value), pulls the slice
// L2 -> warp-private smem, computes its 64-wide K-slice. No group barrier.
// SMEM: Wt[512][64] (128 KB), hsw[8 warps][512], red[8][512].
// =============================================================================
#define GB_CTAS 128

__global__ void __launch_bounds__(256, 1) rnn_persistent_kernel(
    const float* __restrict__ W_hh,   // [HH][HH]
    const float* __restrict__ b_hh,   // [HH]
    float* __restrict__ out)          // y then h_last
{
    extern __shared__ float sm[];
    float* Wt  = sm;                   // [512][64]  Wt[k][c] = W_hh[g0+c][k]
    float* hsw = sm + 512 * 64;        // [8 warps][8 rows * 64 k]
    float* red = hsw + 8 * 512;        // [8 kq][512 outputs]

    const int tid = threadIdx.x;
    const int lane = tid & 31;
    const int gb  = blockIdx.x & 7;    // col-block
    const int rb  = blockIdx.x >> 3;   // row-group
    const int g0  = gb * 64;
    const int row_base = rb * 8;

    // ---- one-time: load W slice transposed into smem (col-fast) ----
    {
        const int c  = tid & 63;
        const int k0 = tid >> 6;       // 0..3
        const float* wsrc = W_hh + (size_t)(g0 + c) * HH;
#pragma unroll 8
        for (int k = k0; k < 512; k += 4)
            Wt[k * 64 + c] = __ldg(wsrc + k);
    }

    // ---- compute-role indices (round-3 mapping) ----
    const int kq    = tid >> 5;        // warp id = K-slice of 64 (= producer id)
    const int rowg  = (tid >> 4) & 1;
    const int colg  = tid & 15;
    const int r0    = rowg * 4;
    const int c0    = colg * 4;

    // ---- epilogue-role indices: outputs o = 2*tid, 2*tid+1 ----
    const int orow  = tid >> 5;        // local row 0..7 (one per warp)
    const int oc    = 2 * (tid & 31);  // local col pair
    const int grow  = row_base + orow; // global recurrence row
    const int b_idx = grow >> 1;       // batch
    const int l_idx = grow & 1;        // layer
    const int gcol  = g0 + oc;         // global column pair base

    const float2 bg  = *(const float2*)&b_hh[gcol];
    float2 xav = *(const float2*)&g_xa[((size_t)b_idx * SS + 0) * HH + gcol];

    const unsigned* prod_flag = &g_flag[rb][kq];   // my warp's producer
    unsigned*       my_flag   = &g_flag[rb][gb];   // this CTA's flag

    float* myh = hsw + kq * 512;       // warp-private staged slice [8][64]

    const size_t Y_ELEMS = (size_t)BB * SS * LL * HH;
    __syncthreads();

    for (int s = 0; s < SS; s++) {
        float v0, v1;
        if (s == 0) {
            v0 = tanhf(xav.x + bg.x);
            v1 = tanhf(xav.y + bg.y);
        } else {
            // wait only for THIS warp's producer to publish step s
            if (lane == 0) {
                unsigned v;
                do {
                    asm volatile("ld.acquire.gpu.u32 %0, [%1];"
                                 : "=r"(v) : "l"(prod_flag));
                } while (v < (unsigned)s);
            }
            __syncwarp();

            // pull producer slice (2 KB) L2 -> warp-private smem
            const float4* src = (const float4*)&g_hsl[s & 1][rb][kq][0];
#pragma unroll
            for (int j = 0; j < 4; j++) {
                const int idx = lane + 32 * j;         // 0..127 float4s
                const float4 v4 = __ldcg(src + idx);
                *(float4*)&myh[idx * 4] = v4;
            }
            __syncwarp();

            // compute 4x4 tile over this warp's K-slice (local k 0..63)
            float acc[4][4];
#pragma unroll
            for (int i = 0; i < 4; i++)
#pragma unroll
                for (int j = 0; j < 4; j++) acc[i][j] = 0.f;

            const float* hp = myh + r0 * 64;
            const float* wp = Wt + (kq * 64) * 64 + c0;
#pragma unroll 2
            for (int k = 0; k < 64; k += 4) {
                const float4 w0 = *(const float4*)(wp + (k + 0) * 64);
                const float4 w1 = *(const float4*)(wp + (k + 1) * 64);
                const float4 w2 = *(const float4*)(wp + (k + 2) * 64);
                const float4 w3 = *(const float4*)(wp + (k + 3) * 64);
                const float4 h0 = *(const float4*)(hp + 0 * 64 + k);
                const float4 h1 = *(const float4*)(hp + 1 * 64 + k);
                const float4 h2 = *(const float4*)(hp + 2 * 64 + k);
                const float4 h3 = *(const float4*)(hp + 3 * 64 + k);
#pragma unroll
                for (int j = 0; j < 4; j++) {
                    const float w0j = (&w0.x)[j], w1j = (&w1.x)[j];
                    const float w2j = (&w2.x)[j], w3j = (&w3.x)[j];
                    acc[0][j] += h0.x * w0j + h0.y * w1j + h0.z * w2j + h0.w * w3j;
                    acc[1][j] += h1.x * w0j + h1.y * w1j + h1.z * w2j + h1.w * w3j;
                    acc[2][j] += h2.x * w0j + h2.y * w1j + h2.z * w2j + h2.w * w3j;
                    acc[3][j] += h3.x * w0j + h3.y * w1j + h3.z * w2j + h3.w * w3j;
                }
            }

            // scatter partials: red[kq][(r0+i)*64 + c0..+3]  (STS.128)
            float* rp = red + kq * 512 + r0 * 64 + c0;
#pragma unroll
            for (int i = 0; i < 4; i++)
                *(float4*)(rp + i * 64) = *(float4*)acc[i];
            __syncthreads();

            // reduce over 8 kq slices for outputs (orow, oc/oc+1)
            const float* q = red + orow * 64 + oc;
            float a0 = 0.f, a1 = 0.f;
#pragma unroll
            for (int z = 0; z < 8; z++) {
                const float2 p = *(const float2*)(q + z * 512);
                a0 += p.x; a1 += p.y;
            }
            v0 = tanhf(a0 + xav.x + bg.x);
            v1 = tanhf(a1 + xav.y + bg.y);
        }

        if (s < SS - 1) {
            // publish slice for step s+1 (buffer (s+1)&1), then flag = s+1
            float* dst = &g_hsl[(s + 1) & 1][rb][gb][orow * 64 + oc];
            asm volatile("st.global.cg.v2.f32 [%0], {%1, %2};"
                         :: "l"(dst), "f"(v0), "f"(v1));
            __syncthreads();
            if (tid == 0)
                asm volatile("st.release.gpu.u32 [%0], %1;"
                             :: "l"(my_flag), "r"((unsigned)(s + 1)));
        }

        // epilogue (overlaps consumers' spins): y writes + next xa prefetch
        {
            float2 yv; yv.x = v0; yv.y = v1;
            *(float2*)&out[(((size_t)b_idx * SS + s) * LL + l_idx) * HH + gcol] = yv;
            if (s == SS - 1) {
                *(float2*)&out[Y_ELEMS + (size_t)grow * HH + gcol] = yv;
            } else {
                xav = *(const float2*)&g_xa[((size_t)b_idx * SS + (s + 1)) * HH + gcol];
            }
        }
    }
}

// =============================================================================
// launch
// =============================================================================
extern "C" void kernel_launch(void* const* d_in, const int* in_sizes, int n_in,
                              void* d_out, int out_size)
{
    const float* x    = (const float*)d_in[0];
    const float* W_ih = (const float*)d_in[1];
    const float* b_ih = (const float*)d_in[2];
    const float* W_hh = (const float*)d_in[3];
    const float* b_hh = (const float*)d_in[4];
    float* out = (float*)d_out;

    // Reset handshake flags (replay safety), then A, then B (stream-ordered)
    reset_flags_kernel<<<1, 128>>>();

    dim3 gridA(HH / 128, MX / 128);
    gemm_xa_kernel<<<gridA, 256>>>(x, W_ih, b_ih);

    const int smemB = (512 * 64 + 8 * 512 + 8 * 512) * (int)sizeof(float);
    cudaFuncSetAttribute(rnn_persistent_kernel,
                         cudaFuncAttributeMaxDynamicSharedMemorySize, smemB);
    rnn_persistent_kernel<<<GB_CTAS, 256, smemB>>>(W_hh, b_hh, out);
}

// round 10
// speedup vs baseline: 1.5781x; 1.5781x over previous
#include <cuda_runtime.h>
#include <cuda_bf16.h>
#include <cstdint>
#include <math.h>

// Problem constants
#define BB 64
#define SS 512
#define II 512
#define HH 512
#define LL 2
#define MROWS (BB * LL)          // 128 recurrence rows
#define MX (BB * SS)             // 32768 rows of xa GEMM

// ---------------- scratch (static device memory; no allocs allowed) ----------
__device__ float g_xa[(size_t)MX * HH];       // 64 MB: xa = x @ W_ih^T + b_ih
__device__ float g_h[2][MROWS * HH];          // double-buffered recurrent state

// per-row-group barrier state (16 groups of 8 CTAs), padded slots
#define RB_GROUPS 16
__device__ unsigned g_cnt[RB_GROUPS * 32];    // arrival counts (return to 0)
__device__ unsigned g_sense[RB_GROUPS * 32];  // 512 toggles -> back to 0

// =============================================================================
// Kernel A: xa[m][n] = sum_k x[m][k] * W_ih[n][k] + b_ih[n]   via tf32 mma.sync
// Grid: (4, 256) CTAs of 128x128. 8 warps as 2 (wr) x 4 (wc); warp = 64m x 32n.
// Fragments loaded straight from gmem (x k-contiguous; W_ih L2-resident).
// mma.sync.aligned.m16n8k8.row.col.f32.tf32.tf32.f32
//   A frag (16x8): a0(g,t) a1(g+8,t) a2(g,t+4) a3(g+8,t+4)
//   B frag (8x8):  b0(t,g) b1(t+4,g)          [B[k][n] = W_ih[n][k]]
//   D frag (16x8): d0(g,2t) d1(g,2t+1) d2(g+8,2t) d3(g+8,2t+1)
// =============================================================================
__device__ __forceinline__ unsigned cvt_tf32(float f) {
    unsigned u;
    asm("cvt.rna.tf32.f32 %0, %1;" : "=r"(u) : "f"(f));
    return u;
}

__global__ void __launch_bounds__(256) gemm_xa_mma_kernel(
    const float* __restrict__ X,      // [MX][II]
    const float* __restrict__ Wih,    // [HH][II]
    const float* __restrict__ bias)   // [HH]
{
    const int m0   = blockIdx.y * 128;
    const int n0   = blockIdx.x * 128;
    const int w    = threadIdx.x >> 5;
    const int lane = threadIdx.x & 31;
    const int g    = lane >> 2;        // groupID 0..7
    const int t    = lane & 3;         // thread-in-group 0..3
    const int wr   = w >> 2;           // 0..1  -> 64 m-rows
    const int wc   = w & 3;            // 0..3  -> 32 n-cols
    const int mbase = m0 + wr * 64;
    const int nbase = n0 + wc * 32;

    float acc[4][4][4];                // [mf][nf][reg]
#pragma unroll
    for (int mf = 0; mf < 4; mf++)
#pragma unroll
        for (int nf = 0; nf < 4; nf++)
#pragma unroll
            for (int r = 0; r < 4; r++) acc[mf][nf][r] = 0.f;

    const float* Xa = X + (size_t)(mbase + g) * II;        // a0/a2 rows
    const float* Xb = X + (size_t)(mbase + g + 8) * II;    // a1/a3 rows
    const float* Wb = Wih + (size_t)(nbase + g) * II;      // b rows (n = nbase+nf*8+g)

#pragma unroll 2
    for (int kt = 0; kt < 64; kt++) {
        const int k0 = kt * 8;

        unsigned a[4][4];
#pragma unroll
        for (int mf = 0; mf < 4; mf++) {
            const int ro = mf * 16 * II;
            a[mf][0] = cvt_tf32(__ldg(Xa + ro + k0 + t));
            a[mf][1] = cvt_tf32(__ldg(Xb + ro + k0 + t));
            a[mf][2] = cvt_tf32(__ldg(Xa + ro + k0 + t + 4));
            a[mf][3] = cvt_tf32(__ldg(Xb + ro + k0 + t + 4));
        }
        unsigned b[4][2];
#pragma unroll
        for (int nf = 0; nf < 4; nf++) {
            const int no = nf * 8 * II;
            b[nf][0] = cvt_tf32(__ldg(Wb + no + k0 + t));
            b[nf][1] = cvt_tf32(__ldg(Wb + no + k0 + t + 4));
        }
#pragma unroll
        for (int mf = 0; mf < 4; mf++)
#pragma unroll
            for (int nf = 0; nf < 4; nf++) {
                asm volatile(
                    "mma.sync.aligned.m16n8k8.row.col.f32.tf32.tf32.f32 "
                    "{%0,%1,%2,%3}, {%4,%5,%6,%7}, {%8,%9}, {%0,%1,%2,%3};"
                    : "+f"(acc[mf][nf][0]), "+f"(acc[mf][nf][1]),
                      "+f"(acc[mf][nf][2]), "+f"(acc[mf][nf][3])
                    : "r"(a[mf][0]), "r"(a[mf][1]), "r"(a[mf][2]), "r"(a[mf][3]),
                      "r"(b[nf][0]), "r"(b[nf][1]));
            }
    }

    // epilogue: add bias, store float2 pairs
#pragma unroll
    for (int nf = 0; nf < 4; nf++) {
        const int col = nbase + nf * 8 + 2 * t;
        const float2 bv = *(const float2*)&bias[col];
#pragma unroll
        for (int mf = 0; mf < 4; mf++) {
            const int row0 = mbase + mf * 16 + g;
            float2 d01, d23;
            d01.x = acc[mf][nf][0] + bv.x;
            d01.y = acc[mf][nf][1] + bv.y;
            d23.x = acc[mf][nf][2] + bv.x;
            d23.y = acc[mf][nf][3] + bv.y;
            *(float2*)&g_xa[(size_t)row0 * HH + col]       = d01;
            *(float2*)&g_xa[(size_t)(row0 + 8) * HH + col] = d23;
        }
    }
}

// =============================================================================
// Kernel B: persistent recurrence (round-3 proven version, unchanged).
// 128 CTAs = 16 row-groups (rb) x 8 col-blocks (gb).
// CTA: rows rb*8..+7, cols gb*64..+63, K=512.
// SMEM: Wt[512][64] (col-fast, 128 KB, resident), hs[8][516], red[8][512].
// 256 threads: kq = tid>>5 (K-slice of 64, one per warp),
//              rowg = (tid>>4)&1 (4 rows), colg = tid&15 (4 cols).
// Thread computes a 4x4 tile over its 64-wide K slice, partials reduced over
// kq through smem. Barrier is per-row-group (8 CTAs).
// =============================================================================
#define GB_CTAS 128
#define GRP 8                      // CTAs per barrier group

__global__ void __launch_bounds__(256, 1) rnn_persistent_kernel(
    const float* __restrict__ W_hh,   // [HH][HH]
    const float* __restrict__ b_hh,   // [HH]
    float* __restrict__ out)          // y then h_last
{
    extern __shared__ float sm[];
    float* Wt  = sm;                   // [512][64]  Wt[k][c] = W_hh[g0+c][k]
    float* hs  = sm + 512 * 64;        // [8][516] (padded)
    float* red = hs + 8 * 516;         // [8 kq][512 outputs]

    const int tid = threadIdx.x;
    const int gb  = blockIdx.x & 7;    // 8 col-blocks
    const int rb  = blockIdx.x >> 3;   // 16 row-groups
    const int g0  = gb * 64;
    const int row_base = rb * 8;

    // ---- one-time: load W slice transposed into smem (col-fast) ----
    {
        const int c  = tid & 63;
        const int k0 = tid >> 6;       // 0..3
        const float* wsrc = W_hh + (size_t)(g0 + c) * HH;
#pragma unroll 8
        for (int k = k0; k < 512; k += 4)
            Wt[k * 64 + c] = __ldg(wsrc + k);
    }

    // ---- compute-role indices ----
    const int kq    = tid >> 5;        // warp id = K-slice
    const int rowg  = (tid >> 4) & 1;
    const int colg  = tid & 15;
    const int kbase = kq * 64;
    const int r0    = rowg * 4;
    const int c0    = colg * 4;

    // ---- epilogue-role indices: outputs o = 2*tid, 2*tid+1 ----
    const int orow  = tid >> 5;        // local row 0..7 (one per warp)
    const int oc    = 2 * (tid & 31);  // local col pair
    const int grow  = row_base + orow; // global recurrence row
    const int b_idx = grow >> 1;       // batch
    const int l_idx = grow & 1;        // layer
    const int gcol  = g0 + oc;         // global column pair base

    const float2 bg  = *(const float2*)&b_hh[gcol];
    float2 xav = *(const float2*)&g_xa[((size_t)b_idx * SS + 0) * HH + gcol];

    unsigned* cnt = &g_cnt[rb * 32];
    unsigned* sns = &g_sense[rb * 32];
    unsigned  sense = 0;

    const size_t Y_ELEMS = (size_t)BB * SS * LL * HH;
    __syncthreads();

    for (int s = 0; s < SS; s++) {
        float v0, v1;
        if (s == 0) {
            v0 = tanhf(xav.x + bg.x);
            v1 = tanhf(xav.y + bg.y);
        } else {
            // wait for group (8 CTAs sharing rb) to finish step s-1
            if (tid == 0) {
                unsigned v;
                do {
                    asm volatile("ld.acquire.gpu.u32 %0, [%1];"
                                 : "=r"(v) : "l"(sns));
                } while (v != sense);
            }
            __syncthreads();

            // stage h rows (8 x 512 = 16 KB) from L2 into padded smem
            const float4* src =
                (const float4*)(&g_h[s & 1][(size_t)row_base * HH]);
#pragma unroll
            for (int j = 0; j < 4; j++) {
                const int idx = tid + j * 256;      // float4 index, 0..1023
                const int r   = idx >> 7;
                const int kk  = idx & 127;
                *(float4*)&hs[r * 516 + kk * 4] = __ldcg(src + idx);
            }
            __syncthreads();

            // compute 4x4 tile over K-slice [kbase, kbase+64)
            float acc[4][4];
#pragma unroll
            for (int i = 0; i < 4; i++)
#pragma unroll
                for (int j = 0; j < 4; j++) acc[i][j] = 0.f;

            const float* hp = hs + r0 * 516 + kbase;
            const float* wp = Wt + kbase * 64 + c0;
#pragma unroll 2
            for (int k = 0; k < 64; k += 4) {
                const float4 w0 = *(const float4*)(wp + (k + 0) * 64);
                const float4 w1 = *(const float4*)(wp + (k + 1) * 64);
                const float4 w2 = *(const float4*)(wp + (k + 2) * 64);
                const float4 w3 = *(const float4*)(wp + (k + 3) * 64);
                const float4 h0 = *(const float4*)(hp + 0 * 516 + k);
                const float4 h1 = *(const float4*)(hp + 1 * 516 + k);
                const float4 h2 = *(const float4*)(hp + 2 * 516 + k);
                const float4 h3 = *(const float4*)(hp + 3 * 516 + k);
#pragma unroll
                for (int j = 0; j < 4; j++) {
                    const float w0j = (&w0.x)[j], w1j = (&w1.x)[j];
                    const float w2j = (&w2.x)[j], w3j = (&w3.x)[j];
                    acc[0][j] += h0.x * w0j + h0.y * w1j + h0.z * w2j + h0.w * w3j;
                    acc[1][j] += h1.x * w0j + h1.y * w1j + h1.z * w2j + h1.w * w3j;
                    acc[2][j] += h2.x * w0j + h2.y * w1j + h2.z * w2j + h2.w * w3j;
                    acc[3][j] += h3.x * w0j + h3.y * w1j + h3.z * w2j + h3.w * w3j;
                }
            }

            // scatter partials: red[kq][(r0+i)*64 + c0..+3]  (STS.128)
            float* rp = red + kq * 512 + r0 * 64 + c0;
#pragma unroll
            for (int i = 0; i < 4; i++)
                *(float4*)(rp + i * 64) = *(float4*)acc[i];
            __syncthreads();

            // reduce over 8 kq slices for outputs (orow, oc/oc+1)
            const float* q = red + orow * 64 + oc;
            float a0 = 0.f, a1 = 0.f;
#pragma unroll
            for (int z = 0; z < 8; z++) {
                const float2 p = *(const float2*)(q + z * 512);
                a0 += p.x; a1 += p.y;
            }
            v0 = tanhf(a0 + xav.x + bg.x);
            v1 = tanhf(a1 + xav.y + bg.y);
        }

        // publish h for next step (straight to L2)
        {
            float2* hdst = (float2*)&g_h[(s + 1) & 1][(size_t)grow * HH + gcol];
            asm volatile("st.global.cg.v2.f32 [%0], {%1, %2};"
                         :: "l"(hdst), "f"(v0), "f"(v1));
        }
        __syncthreads();

        // group barrier arrival (release publishes this step's h writes)
        if (tid == 0) {
            unsigned old;
            asm volatile("atom.add.release.gpu.u32 %0, [%1], %2;"
                         : "=r"(old) : "l"(cnt), "r"(1u));
            if (old == GRP - 1u) {
                asm volatile("st.relaxed.gpu.u32 [%0], %1;"
                             :: "l"(cnt), "r"(0u));
                asm volatile("st.release.gpu.u32 [%0], %1;"
                             :: "l"(sns), "r"(sense ^ 1u));
            }
        }
        sense ^= 1u;

        // epilogue overlaps peers' spin: y writes + next xa prefetch
        {
            float2 yv; yv.x = v0; yv.y = v1;
            *(float2*)&out[(((size_t)b_idx * SS + s) * LL + l_idx) * HH + gcol] = yv;
            if (s == SS - 1) {
                *(float2*)&out[Y_ELEMS + (size_t)grow * HH + gcol] = yv;
            } else {
                xav = *(const float2*)&g_xa[((size_t)b_idx * SS + (s + 1)) * HH + gcol];
            }
        }
    }
}

// =============================================================================
// launch
// =============================================================================
extern "C" void kernel_launch(void* const* d_in, const int* in_sizes, int n_in,
                              void* d_out, int out_size)
{
    const float* x    = (const float*)d_in[0];
    const float* W_ih = (const float*)d_in[1];
    const float* b_ih = (const float*)d_in[2];
    const float* W_hh = (const float*)d_in[3];
    const float* b_hh = (const float*)d_in[4];
    float* out = (float*)d_out;

    // Kernel A: xa = x @ W_ih^T + b_ih  (tf32 mma.sync)
    dim3 gridA(HH / 128, MX / 128);   // (4, 256)
    gemm_xa_mma_kernel<<<gridA, 256>>>(x, W_ih, b_ih);

    // Kernel B: persistent recurrence (round-3 proven)
    const int smemB = (512 * 64 + 8 * 516 + 8 * 512) * (int)sizeof(float);
    cudaFuncSetAttribute(rnn_persistent_kernel,
                         cudaFuncAttributeMaxDynamicSharedMemorySize, smemB);
    rnn_persistent_kernel<<<GB_CTAS, 256, smemB>>>(W_hh, b_hh, out);
}